// round 11
// baseline (speedup 1.0000x reference)
#include <cuda_runtime.h>

// DNAShapeNet fused kernel, R7: R4 structure (512 thr, 18-pos chunks,
// channel-pair f32x2) + per-warp cin rotation + cin-loop unroll 2.
// (R6 retry with the thread mapping fixed: cp=tid>>5, j=tid&31.)

#define BATCH    128
#define SEQ      8192
#define TSIZE    512
#define NTHREADS 512
#define WPAD     592
#define HALO     7

typedef unsigned long long ull;

// ---- smem layout (float offsets) ----
#define OFF_BUFA 0
#define OFF_BUFB (OFF_BUFA + 32*WPAD)
#define OFF_W0   (OFF_BUFB + 32*WPAD)
#define OFF_W1   (OFF_W0 + 384)
#define OFF_W2   (OFF_W1 + 3072)
#define OFF_W3   (OFF_W2 + 5120)
#define OFF_SC   (OFF_W3 + 7168)
#define OFF_SH   (OFF_SC + 128)
#define OFF_BI   (OFF_SH + 128)
#define OFF_FW1  (OFF_BI + 128)
#define OFF_FB1  (OFF_FW1 + 512)
#define OFF_FW2  (OFF_FB1 + 16)
#define OFF_FB2  (OFF_FW2 + 16)
#define SMEM_FLOATS (OFF_FB2 + 1)
#define SMEM_BYTES  (SMEM_FLOATS * 4)

struct Ptrs {
    const float* x;
    const float* w[4];
    const float* b[4];
    const float* g[4];
    const float* bb[4];
    const float* rm[4];
    const float* rv[4];
    const float* fw1;
    const float* fb1;
    const float* fw2;
    const float* fb2;
};

__device__ __forceinline__ ull pack2(float lo, float hi) {
    ull r;
    asm("mov.b64 %0, {%1, %2};" : "=l"(r) : "f"(lo), "f"(hi));
    return r;
}
__device__ __forceinline__ void unpack2(ull v, float& lo, float& hi) {
    asm("mov.b64 {%0, %1}, %2;" : "=f"(lo), "=f"(hi) : "l"(v));
}
__device__ __forceinline__ ull fma2(ull a, ull b, ull c) {
    ull d;
    asm("fma.rn.f32x2 %0, %1, %2, %3;" : "=l"(d) : "l"(a), "l"(b), "l"(c));
    return d;
}

// CH output positions for one input channel, channel-pair packed.
template<int K, int SOFF, int CH>
__device__ __forceinline__ void conv_chunk_cp(const float* __restrict__ xin,
                                              const ull* __restrict__ wp,
                                              ull* __restrict__ acc)
{
    constexpr int NS = SOFF + CH + K - 1;   // scalars spanned from even base
    constexpr int NP = (NS + 1) >> 1;       // float2 loads

    float s[2 * NP];
#pragma unroll
    for (int i = 0; i < NP; ++i) {
        float2 v = ((const float2*)xin)[i];
        s[2 * i] = v.x; s[2 * i + 1] = v.y;
    }

    ull bb[NS];                             // broadcast pairs {s,s}
#pragma unroll
    for (int u = SOFF; u < NS; ++u) bb[u] = pack2(s[u], s[u]);

#pragma unroll
    for (int t = 0; t < K; ++t)
#pragma unroll
        for (int p = 0; p < CH; ++p)
            acc[p] = fma2(bb[SOFF + p + t], wp[t], acc[p]);
}

// One conv+ReLU+BN layer, smem -> smem. Thread (cp, j) computes channels
// {2cp, 2cp+1} at 18 positions starting at LOFF + j*18, cp in [0,16), j in [0,32).
// rot: per-warp cin-loop start offset (multiple of 8, CIN=32 only).
template <int CIN, int K, int WOUT, int LOFF, int UNROLL>
__device__ __forceinline__ void conv_layer_cp(
    const float* __restrict__ sin, float* __restrict__ sout,
    const float* __restrict__ wint,
    const float* __restrict__ sc, const float* __restrict__ sh,
    const float* __restrict__ bi,
    int cp, int j, int rot, int seq_base)
{
    constexpr int H = K / 2;
    constexpr int DELTA = (LOFF - H) & 1;        // parity fix -> even base

    ull acc[18];
    const ull z = pack2(0.f, 0.f);
#pragma unroll
    for (int p = 0; p < 18; ++p) acc[p] = z;

    const int abase = (LOFF - H - DELTA) + j * 18;   // even

#pragma unroll UNROLL
    for (int ii = 0; ii < CIN; ++ii) {
        const int cin = (ii + rot) & (CIN - 1);
        const ull* wsm = (const ull*)(wint + (cp * CIN + cin) * (2 * K));
        ull wp[K];
#pragma unroll
        for (int t = 0; t < K; ++t) wp[t] = wsm[t];   // LDS.64, warp-uniform

        const float* xin = sin + cin * WPAD + abase;
        conv_chunk_cp<K, DELTA, 18>(xin, wp, acc);
    }

    const int co0 = 2 * cp;
    const float sc0 = sc[co0], sh0 = sh[co0], bi0 = bi[co0];
    const float sc1 = sc[co0 + 1], sh1 = sh[co0 + 1], bi1 = bi[co0 + 1];
    float* o0 = sout + co0 * WPAD;
    float* o1 = o0 + WPAD;

#pragma unroll
    for (int i = 0; i < 18; ++i) {
        int pl = j * 18 + i;
        if (pl < WOUT) {
            int u = LOFF + pl;
            int seq = seq_base + u;
            bool inb = (seq >= 0 && seq < SEQ);
            float a0, a1;
            unpack2(acc[i], a0, a1);
            float y0 = fmaxf(a0 + bi0, 0.f);
            float y1 = fmaxf(a1 + bi1, 0.f);
            o0[u] = inb ? fmaf(y0, sc0, sh0) : 0.f;
            o1[u] = inb ? fmaf(y1, sc1, sh1) : 0.f;
        }
    }
}

__global__ void __launch_bounds__(NTHREADS, 1)
dna_fused_kernel(Ptrs P, float* __restrict__ out)
{
    extern __shared__ float sm[];
    const int tid = threadIdx.x;
    const int ts  = blockIdx.x * TSIZE;
    const int b   = blockIdx.y;
    const int seq_base = ts - HALO;

    float* bufA = sm + OFF_BUFA;
    float* bufB = sm + OFF_BUFB;
    float* sW[4] = { sm + OFF_W0, sm + OFF_W1, sm + OFF_W2, sm + OFF_W3 };
    float* sSC = sm + OFF_SC;
    float* sSH = sm + OFF_SH;
    float* sBI = sm + OFF_BI;
    float* sFW1 = sm + OFF_FW1;
    float* sFB1 = sm + OFF_FB1;
    float* sFW2 = sm + OFF_FW2;
    float* sFB2 = sm + OFF_FB2;

    // phase 1: halo-only zero fill of both activation buffers.
    {
        constexpr int ZPR = 8 + (WPAD - 512);   // 88 zeros per row
        for (int idx = tid; idx < 64 * ZPR; idx += NTHREADS) {
            int r = idx / ZPR, c = idx - r * ZPR;
            int u = (c < 8) ? c : (504 + c);
            sm[r * WPAD + u] = 0.f;
        }
    }

    const int cinK[4] = { 4 * 3, 32 * 3, 32 * 5, 32 * 7 };
#pragma unroll
    for (int l = 0; l < 4; ++l) {
        const int n = cinK[l];                 // per-channel weight count
        for (int i = tid; i < 16 * n; i += NTHREADS) {
            int cp = i / n, r = i - cp * n;
            sW[l][2 * i]     = P.w[l][(2 * cp)     * n + r];
            sW[l][2 * i + 1] = P.w[l][(2 * cp + 1) * n + r];
        }
    }

    for (int i = tid; i < 16 * 32; i += NTHREADS) sFW1[i] = P.fw1[i];
    if (tid < 16) { sFB1[tid] = P.fb1[tid]; sFW2[tid] = P.fw2[tid]; }
    if (tid == 0) sFB2[0] = P.fb2[0];

    if (tid < 128) {
        int l = tid >> 5, c = tid & 31;
        float inv = P.g[l][c] * rsqrtf(P.rv[l][c] + 1e-5f);
        sSC[tid] = inv;
        sSH[tid] = P.bb[l][c] - P.rm[l][c] * inv;
        sBI[tid] = P.b[l][c];
    }
    __syncthreads();

    // phase 2: input tile (4 channels, width 526) over the zeroed halo
    constexpr int WIN = TSIZE + 2 * HALO;   // 526
    for (int idx = tid; idx < 4 * WIN; idx += NTHREADS) {
        int cin = idx / WIN;
        int u = idx - cin * WIN;
        int seq = seq_base + u;
        if (seq >= 0 && seq < SEQ)
            bufA[cin * WPAD + u] = P.x[(b * 4 + cin) * SEQ + seq];
    }
    __syncthreads();

    const int cp  = tid >> 5;                  // warp -> channel pair [0,16)
    const int j   = tid & 31;                  // lane -> 18-pos slice [0,32)
    const int rot = (cp & 3) << 3;             // warp-phase cin rotation (x8)

    conv_layer_cp<4, 3, 524, 1, 4>(bufA, bufB, sW[0], sSC +  0, sSH +  0, sBI +  0, cp, j, 0,   seq_base);
    __syncthreads();
    conv_layer_cp<32, 3, 522, 2, 2>(bufB, bufA, sW[1], sSC + 32, sSH + 32, sBI + 32, cp, j, rot, seq_base);
    __syncthreads();
    conv_layer_cp<32, 5, 518, 4, 2>(bufA, bufB, sW[2], sSC + 64, sSH + 64, sBI + 64, cp, j, rot, seq_base);
    __syncthreads();
    conv_layer_cp<32, 7, 512, 7, 2>(bufB, bufA, sW[3], sSC + 96, sSH + 96, sBI + 96, cp, j, rot, seq_base);
    __syncthreads();

    // ---- per-position MLP: 32 -> 16 (ReLU) -> 1 ; one thread per position ----
    float yc[32];
#pragma unroll
    for (int c = 0; c < 32; ++c) yc[c] = bufA[c * WPAD + HALO + tid];

    float o = sFB2[0];
#pragma unroll
    for (int i = 0; i < 16; ++i) {
        float h = sFB1[i];
#pragma unroll
        for (int c = 0; c < 32; ++c) h = fmaf(sFW1[i * 32 + c], yc[c], h);
        o = fmaf(fmaxf(h, 0.f), sFW2[i], o);
    }
    out[b * SEQ + ts + tid] = o;
}

extern "C" void kernel_launch(void* const* d_in, const int* in_sizes, int n_in,
                              void* d_out, int out_size)
{
    Ptrs P;
    P.x = (const float*)d_in[0];
    for (int l = 0; l < 4; ++l) {
        P.w[l]  = (const float*)d_in[1 + 6 * l];
        P.b[l]  = (const float*)d_in[2 + 6 * l];
        P.g[l]  = (const float*)d_in[3 + 6 * l];
        P.bb[l] = (const float*)d_in[4 + 6 * l];
        P.rm[l] = (const float*)d_in[5 + 6 * l];
        P.rv[l] = (const float*)d_in[6 + 6 * l];
    }
    P.fw1 = (const float*)d_in[25];
    P.fb1 = (const float*)d_in[26];
    P.fw2 = (const float*)d_in[27];
    P.fb2 = (const float*)d_in[28];

    cudaFuncSetAttribute(dna_fused_kernel,
                         cudaFuncAttributeMaxDynamicSharedMemorySize, SMEM_BYTES);

    dim3 grid(SEQ / TSIZE, BATCH);
    dna_fused_kernel<<<grid, NTHREADS, SMEM_BYTES>>>(P, (float*)d_out);
}

// round 13
// speedup vs baseline: 1.0015x; 1.0015x over previous
#include <cuda_runtime.h>

// DNAShapeNet fused kernel, R10: R4 (705us) + clean two-range cin rotation.
// Warps of one SMSP start the channel loop at different offsets (0/8/16/24)
// via two plain loops — no masking, no extra ALU — so their LDS bursts and
// FMA bursts interleave instead of phase-locking.

#define BATCH    128
#define SEQ      8192
#define TSIZE    512
#define NTHREADS 512
#define WPAD     592
#define HALO     7

typedef unsigned long long ull;

// ---- smem layout (float offsets) ----
#define OFF_BUFA 0
#define OFF_BUFB (OFF_BUFA + 32*WPAD)
#define OFF_W0   (OFF_BUFB + 32*WPAD)
#define OFF_W1   (OFF_W0 + 384)
#define OFF_W2   (OFF_W1 + 3072)
#define OFF_W3   (OFF_W2 + 5120)
#define OFF_SC   (OFF_W3 + 7168)
#define OFF_SH   (OFF_SC + 128)
#define OFF_BI   (OFF_SH + 128)
#define OFF_FW1  (OFF_BI + 128)
#define OFF_FB1  (OFF_FW1 + 512)
#define OFF_FW2  (OFF_FB1 + 16)
#define OFF_FB2  (OFF_FW2 + 16)
#define SMEM_FLOATS (OFF_FB2 + 1)
#define SMEM_BYTES  (SMEM_FLOATS * 4)

struct Ptrs {
    const float* x;
    const float* w[4];
    const float* b[4];
    const float* g[4];
    const float* bb[4];
    const float* rm[4];
    const float* rv[4];
    const float* fw1;
    const float* fb1;
    const float* fw2;
    const float* fb2;
};

__device__ __forceinline__ ull pack2(float lo, float hi) {
    ull r;
    asm("mov.b64 %0, {%1, %2};" : "=l"(r) : "f"(lo), "f"(hi));
    return r;
}
__device__ __forceinline__ void unpack2(ull v, float& lo, float& hi) {
    asm("mov.b64 {%0, %1}, %2;" : "=f"(lo), "=f"(hi) : "l"(v));
}
__device__ __forceinline__ ull fma2(ull a, ull b, ull c) {
    ull d;
    asm("fma.rn.f32x2 %0, %1, %2, %3;" : "=l"(d) : "l"(a), "l"(b), "l"(c));
    return d;
}

// CH output positions for one input channel, channel-pair packed.
template<int K, int SOFF, int CH>
__device__ __forceinline__ void conv_chunk_cp(const float* __restrict__ xin,
                                              const ull* __restrict__ wp,
                                              ull* __restrict__ acc)
{
    constexpr int NS = SOFF + CH + K - 1;   // scalars spanned from even base
    constexpr int NP = (NS + 1) >> 1;       // float2 loads

    float s[2 * NP];
#pragma unroll
    for (int i = 0; i < NP; ++i) {
        float2 v = ((const float2*)xin)[i];
        s[2 * i] = v.x; s[2 * i + 1] = v.y;
    }

    ull bb[NS];                             // broadcast pairs {s,s}
#pragma unroll
    for (int u = SOFF; u < NS; ++u) bb[u] = pack2(s[u], s[u]);

#pragma unroll
    for (int t = 0; t < K; ++t)
#pragma unroll
        for (int p = 0; p < CH; ++p)
            acc[p] = fma2(bb[SOFF + p + t], wp[t], acc[p]);
}

// BN/ReLU epilogue + store, shared by both layer variants.
template <int WOUT, int LOFF>
__device__ __forceinline__ void store_outputs(
    float* __restrict__ sout, const ull* __restrict__ acc,
    const float* __restrict__ sc, const float* __restrict__ sh,
    const float* __restrict__ bi, int cp, int j, int seq_base)
{
    const int co0 = 2 * cp;
    const float sc0 = sc[co0], sh0 = sh[co0], bi0 = bi[co0];
    const float sc1 = sc[co0 + 1], sh1 = sh[co0 + 1], bi1 = bi[co0 + 1];
    float* o0 = sout + co0 * WPAD;
    float* o1 = o0 + WPAD;

#pragma unroll
    for (int i = 0; i < 18; ++i) {
        int pl = j * 18 + i;
        if (pl < WOUT) {
            int u = LOFF + pl;
            int seq = seq_base + u;
            bool inb = (seq >= 0 && seq < SEQ);
            float a0, a1;
            unpack2(acc[i], a0, a1);
            float y0 = fmaxf(a0 + bi0, 0.f);
            float y1 = fmaxf(a1 + bi1, 0.f);
            o0[u] = inb ? fmaf(y0, sc0, sh0) : 0.f;
            o1[u] = inb ? fmaf(y1, sc1, sh1) : 0.f;
        }
    }
}

// Layer 1 (CIN=4): fully unrolled, no rotation (identical to R4).
template <int K, int WOUT, int LOFF>
__device__ __forceinline__ void conv_layer_l1(
    const float* __restrict__ sin, float* __restrict__ sout,
    const float* __restrict__ wint,
    const float* __restrict__ sc, const float* __restrict__ sh,
    const float* __restrict__ bi,
    int cp, int j, int seq_base)
{
    constexpr int H = K / 2;
    constexpr int DELTA = (LOFF - H) & 1;

    ull acc[18];
    const ull z = pack2(0.f, 0.f);
#pragma unroll
    for (int p = 0; p < 18; ++p) acc[p] = z;

    const int abase = (LOFF - H - DELTA) + j * 18;

#pragma unroll 4
    for (int cin = 0; cin < 4; ++cin) {
        const ull* wsm = (const ull*)(wint + (cp * 4 + cin) * (2 * K));
        ull wp[K];
#pragma unroll
        for (int t = 0; t < K; ++t) wp[t] = wsm[t];
        conv_chunk_cp<K, DELTA, 18>(sin + cin * WPAD + abase, wp, acc);
    }
    store_outputs<WOUT, LOFF>(sout, acc, sc, sh, bi, cp, j, seq_base);
}

// Layers 2-4 (CIN=32): two-range rotation. Warp-dependent start offset `rot`
// desynchronizes LDS bursts across the 4 warps of an SMSP; plain loop ranges
// keep addressing warp-uniform (no per-iteration masking).
template <int K, int WOUT, int LOFF>
__device__ __forceinline__ void conv_layer_rot(
    const float* __restrict__ sin, float* __restrict__ sout,
    const float* __restrict__ wint,
    const float* __restrict__ sc, const float* __restrict__ sh,
    const float* __restrict__ bi,
    int cp, int j, int rot, int seq_base)
{
    constexpr int H = K / 2;
    constexpr int DELTA = (LOFF - H) & 1;

    ull acc[18];
    const ull z = pack2(0.f, 0.f);
#pragma unroll
    for (int p = 0; p < 18; ++p) acc[p] = z;

    const int abase = (LOFF - H - DELTA) + j * 18;

#pragma unroll 1
    for (int cin = rot; cin < 32; ++cin) {
        const ull* wsm = (const ull*)(wint + (cp * 32 + cin) * (2 * K));
        ull wp[K];
#pragma unroll
        for (int t = 0; t < K; ++t) wp[t] = wsm[t];
        conv_chunk_cp<K, DELTA, 18>(sin + cin * WPAD + abase, wp, acc);
    }
#pragma unroll 1
    for (int cin = 0; cin < rot; ++cin) {
        const ull* wsm = (const ull*)(wint + (cp * 32 + cin) * (2 * K));
        ull wp[K];
#pragma unroll
        for (int t = 0; t < K; ++t) wp[t] = wsm[t];
        conv_chunk_cp<K, DELTA, 18>(sin + cin * WPAD + abase, wp, acc);
    }
    store_outputs<WOUT, LOFF>(sout, acc, sc, sh, bi, cp, j, seq_base);
}

__global__ void __launch_bounds__(NTHREADS, 1)
dna_fused_kernel(Ptrs P, float* __restrict__ out)
{
    extern __shared__ float sm[];
    const int tid = threadIdx.x;
    const int ts  = blockIdx.x * TSIZE;
    const int b   = blockIdx.y;
    const int seq_base = ts - HALO;

    float* bufA = sm + OFF_BUFA;
    float* bufB = sm + OFF_BUFB;
    float* sW[4] = { sm + OFF_W0, sm + OFF_W1, sm + OFF_W2, sm + OFF_W3 };
    float* sSC = sm + OFF_SC;
    float* sSH = sm + OFF_SH;
    float* sBI = sm + OFF_BI;
    float* sFW1 = sm + OFF_FW1;
    float* sFB1 = sm + OFF_FB1;
    float* sFW2 = sm + OFF_FW2;
    float* sFB2 = sm + OFF_FB2;

    // phase 1: halo-only zero fill of both activation buffers.
    {
        constexpr int ZPR = 8 + (WPAD - 512);   // 88 zeros per row
        for (int idx = tid; idx < 64 * ZPR; idx += NTHREADS) {
            int r = idx / ZPR, c = idx - r * ZPR;
            int u = (c < 8) ? c : (504 + c);
            sm[r * WPAD + u] = 0.f;
        }
    }

    const int cinK[4] = { 4 * 3, 32 * 3, 32 * 5, 32 * 7 };
#pragma unroll
    for (int l = 0; l < 4; ++l) {
        const int n = cinK[l];                 // per-channel weight count
        for (int i = tid; i < 16 * n; i += NTHREADS) {
            int cp = i / n, r = i - cp * n;
            sW[l][2 * i]     = P.w[l][(2 * cp)     * n + r];
            sW[l][2 * i + 1] = P.w[l][(2 * cp + 1) * n + r];
        }
    }

    for (int i = tid; i < 16 * 32; i += NTHREADS) sFW1[i] = P.fw1[i];
    if (tid < 16) { sFB1[tid] = P.fb1[tid]; sFW2[tid] = P.fw2[tid]; }
    if (tid == 0) sFB2[0] = P.fb2[0];

    if (tid < 128) {
        int l = tid >> 5, c = tid & 31;
        float inv = P.g[l][c] * rsqrtf(P.rv[l][c] + 1e-5f);
        sSC[tid] = inv;
        sSH[tid] = P.bb[l][c] - P.rm[l][c] * inv;
        sBI[tid] = P.b[l][c];
    }
    __syncthreads();

    // phase 2: input tile (4 channels, width 526) over the zeroed halo
    constexpr int WIN = TSIZE + 2 * HALO;   // 526
    for (int idx = tid; idx < 4 * WIN; idx += NTHREADS) {
        int cin = idx / WIN;
        int u = idx - cin * WIN;
        int seq = seq_base + u;
        if (seq >= 0 && seq < SEQ)
            bufA[cin * WPAD + u] = P.x[(b * 4 + cin) * SEQ + seq];
    }
    __syncthreads();

    const int cp  = tid >> 5;                  // warp -> channel pair [0,16)
    const int j   = tid & 31;                  // lane -> 18-pos slice [0,32)
    const int rot = (cp & 3) << 3;             // per-warp cin start: 0/8/16/24

    conv_layer_l1<3, 524, 1>(bufA, bufB, sW[0], sSC +  0, sSH +  0, sBI +  0, cp, j, seq_base);
    __syncthreads();
    conv_layer_rot<3, 522, 2>(bufB, bufA, sW[1], sSC + 32, sSH + 32, sBI + 32, cp, j, rot, seq_base);
    __syncthreads();
    conv_layer_rot<5, 518, 4>(bufA, bufB, sW[2], sSC + 64, sSH + 64, sBI + 64, cp, j, rot, seq_base);
    __syncthreads();
    conv_layer_rot<7, 512, 7>(bufB, bufA, sW[3], sSC + 96, sSH + 96, sBI + 96, cp, j, rot, seq_base);
    __syncthreads();

    // ---- per-position MLP: 32 -> 16 (ReLU) -> 1 ; one thread per position ----
    float yc[32];
#pragma unroll
    for (int c = 0; c < 32; ++c) yc[c] = bufA[c * WPAD + HALO + tid];

    float o = sFB2[0];
#pragma unroll
    for (int i = 0; i < 16; ++i) {
        float h = sFB1[i];
#pragma unroll
        for (int c = 0; c < 32; ++c) h = fmaf(sFW1[i * 32 + c], yc[c], h);
        o = fmaf(fmaxf(h, 0.f), sFW2[i], o);
    }
    out[b * SEQ + ts + tid] = o;
}

extern "C" void kernel_launch(void* const* d_in, const int* in_sizes, int n_in,
                              void* d_out, int out_size)
{
    Ptrs P;
    P.x = (const float*)d_in[0];
    for (int l = 0; l < 4; ++l) {
        P.w[l]  = (const float*)d_in[1 + 6 * l];
        P.b[l]  = (const float*)d_in[2 + 6 * l];
        P.g[l]  = (const float*)d_in[3 + 6 * l];
        P.bb[l] = (const float*)d_in[4 + 6 * l];
        P.rm[l] = (const float*)d_in[5 + 6 * l];
        P.rv[l] = (const float*)d_in[6 + 6 * l];
    }
    P.fw1 = (const float*)d_in[25];
    P.fb1 = (const float*)d_in[26];
    P.fw2 = (const float*)d_in[27];
    P.fb2 = (const float*)d_in[28];

    cudaFuncSetAttribute(dna_fused_kernel,
                         cudaFuncAttributeMaxDynamicSharedMemorySize, SMEM_BYTES);

    dim3 grid(SEQ / TSIZE, BATCH);
    dna_fused_kernel<<<grid, NTHREADS, SMEM_BYTES>>>(P, (float*)d_out);
}

// round 14
// speedup vs baseline: 1.1065x; 1.1048x over previous
#include <cuda_runtime.h>

// DNAShapeNet fused kernel, R11: R4 (705us) + software-pipelined cin loop.
// Register double-buffer (vA/vB) prefetches cin+1's input float2s before
// cin's pack+FMA block, hiding LDS latency. Same instruction count as R4.

#define BATCH    128
#define SEQ      8192
#define TSIZE    512
#define NTHREADS 512
#define WPAD     592
#define HALO     7

typedef unsigned long long ull;

// ---- smem layout (float offsets) ----
#define OFF_BUFA 0
#define OFF_BUFB (OFF_BUFA + 32*WPAD)
#define OFF_W0   (OFF_BUFB + 32*WPAD)
#define OFF_W1   (OFF_W0 + 384)
#define OFF_W2   (OFF_W1 + 3072)
#define OFF_W3   (OFF_W2 + 5120)
#define OFF_SC   (OFF_W3 + 7168)
#define OFF_SH   (OFF_SC + 128)
#define OFF_BI   (OFF_SH + 128)
#define OFF_FW1  (OFF_BI + 128)
#define OFF_FB1  (OFF_FW1 + 512)
#define OFF_FW2  (OFF_FB1 + 16)
#define OFF_FB2  (OFF_FW2 + 16)
#define SMEM_FLOATS (OFF_FB2 + 1)
#define SMEM_BYTES  (SMEM_FLOATS * 4)

struct Ptrs {
    const float* x;
    const float* w[4];
    const float* b[4];
    const float* g[4];
    const float* bb[4];
    const float* rm[4];
    const float* rv[4];
    const float* fw1;
    const float* fb1;
    const float* fw2;
    const float* fb2;
};

__device__ __forceinline__ ull pack2(float lo, float hi) {
    ull r;
    asm("mov.b64 %0, {%1, %2};" : "=l"(r) : "f"(lo), "f"(hi));
    return r;
}
__device__ __forceinline__ void unpack2(ull v, float& lo, float& hi) {
    asm("mov.b64 {%0, %1}, %2;" : "=f"(lo), "=f"(hi) : "l"(v));
}
__device__ __forceinline__ ull fma2(ull a, ull b, ull c) {
    ull d;
    asm("fma.rn.f32x2 %0, %1, %2, %3;" : "=l"(d) : "l"(a), "l"(b), "l"(c));
    return d;
}

// ---------- R4 chunk helper (used by layer 1 only) ----------
template<int K, int SOFF, int CH>
__device__ __forceinline__ void conv_chunk_cp(const float* __restrict__ xin,
                                              const ull* __restrict__ wp,
                                              ull* __restrict__ acc)
{
    constexpr int NS = SOFF + CH + K - 1;
    constexpr int NP = (NS + 1) >> 1;

    float s[2 * NP];
#pragma unroll
    for (int i = 0; i < NP; ++i) {
        float2 v = ((const float2*)xin)[i];
        s[2 * i] = v.x; s[2 * i + 1] = v.y;
    }

    ull bb[NS];
#pragma unroll
    for (int u = SOFF; u < NS; ++u) bb[u] = pack2(s[u], s[u]);

#pragma unroll
    for (int t = 0; t < K; ++t)
#pragma unroll
        for (int p = 0; p < CH; ++p)
            acc[p] = fma2(bb[SOFF + p + t], wp[t], acc[p]);
}

// ---------- pipelined machinery (layers 2-4) ----------
// NS = SOFF + 18 + K - 1 scalars spanned; NP float2 loads.
template<int K, int SOFF>
__device__ __forceinline__ void load_f2(const float* __restrict__ xin,
                                        float2* __restrict__ v)
{
    constexpr int NP = (SOFF + K + 18) >> 1;
#pragma unroll
    for (int i = 0; i < NP; ++i) v[i] = ((const float2*)xin)[i];
}

// pack-on-consume FMA block: for each scalar u, pack once, fan out to taps.
template<int K, int SOFF>
__device__ __forceinline__ void fma_f2(const float2* __restrict__ v,
                                       const ull* __restrict__ wp,
                                       ull* __restrict__ acc)
{
    constexpr int NS = SOFF + K + 17;
    constexpr int NP = (SOFF + K + 18) >> 1;
#pragma unroll
    for (int q = 0; q < NP; ++q) {
#pragma unroll
        for (int e = 0; e < 2; ++e) {
            const int u = 2 * q + e;
            if (u >= SOFF && u < NS) {
                float s = e ? v[q].y : v[q].x;
                ull b = pack2(s, s);
#pragma unroll
                for (int t = 0; t < K; ++t) {
                    int p = u - SOFF - t;
                    if (p >= 0 && p < 18)
                        acc[p] = fma2(b, wp[t], acc[p]);
                }
            }
        }
    }
}

// BN/ReLU epilogue + store.
template <int WOUT, int LOFF>
__device__ __forceinline__ void store_outputs(
    float* __restrict__ sout, const ull* __restrict__ acc,
    const float* __restrict__ sc, const float* __restrict__ sh,
    const float* __restrict__ bi, int cp, int j, int seq_base)
{
    const int co0 = 2 * cp;
    const float sc0 = sc[co0], sh0 = sh[co0], bi0 = bi[co0];
    const float sc1 = sc[co0 + 1], sh1 = sh[co0 + 1], bi1 = bi[co0 + 1];
    float* o0 = sout + co0 * WPAD;
    float* o1 = o0 + WPAD;

#pragma unroll
    for (int i = 0; i < 18; ++i) {
        int pl = j * 18 + i;
        if (pl < WOUT) {
            int u = LOFF + pl;
            int seq = seq_base + u;
            bool inb = (seq >= 0 && seq < SEQ);
            float a0, a1;
            unpack2(acc[i], a0, a1);
            float y0 = fmaxf(a0 + bi0, 0.f);
            float y1 = fmaxf(a1 + bi1, 0.f);
            o0[u] = inb ? fmaf(y0, sc0, sh0) : 0.f;
            o1[u] = inb ? fmaf(y1, sc1, sh1) : 0.f;
        }
    }
}

// Layer 1 (CIN=4): R4 style, fully unrolled.
template <int K, int WOUT, int LOFF>
__device__ __forceinline__ void conv_layer_l1(
    const float* __restrict__ sin, float* __restrict__ sout,
    const float* __restrict__ wint,
    const float* __restrict__ sc, const float* __restrict__ sh,
    const float* __restrict__ bi,
    int cp, int j, int seq_base)
{
    constexpr int H = K / 2;
    constexpr int DELTA = (LOFF - H) & 1;

    ull acc[18];
    const ull z = pack2(0.f, 0.f);
#pragma unroll
    for (int p = 0; p < 18; ++p) acc[p] = z;

    const int abase = (LOFF - H - DELTA) + j * 18;

#pragma unroll 4
    for (int cin = 0; cin < 4; ++cin) {
        const ull* wsm = (const ull*)(wint + (cp * 4 + cin) * (2 * K));
        ull wp[K];
#pragma unroll
        for (int t = 0; t < K; ++t) wp[t] = wsm[t];
        conv_chunk_cp<K, DELTA, 18>(sin + cin * WPAD + abase, wp, acc);
    }
    store_outputs<WOUT, LOFF>(sout, acc, sc, sh, bi, cp, j, seq_base);
}

// Layers 2-4 (CIN=32): software-pipelined register double-buffer over cin.
template <int K, int WOUT, int LOFF>
__device__ __forceinline__ void conv_layer_pf(
    const float* __restrict__ sin, float* __restrict__ sout,
    const float* __restrict__ wint,
    const float* __restrict__ sc, const float* __restrict__ sh,
    const float* __restrict__ bi,
    int cp, int j, int seq_base)
{
    constexpr int H = K / 2;
    constexpr int DELTA = (LOFF - H) & 1;
    constexpr int NP = (DELTA + K + 18) >> 1;

    ull acc[18];
    const ull z = pack2(0.f, 0.f);
#pragma unroll
    for (int p = 0; p < 18; ++p) acc[p] = z;

    const int abase = (LOFF - H - DELTA) + j * 18;
    const float* xin = sin + abase;
    const ull* wbase = (const ull*)(wint + cp * 32 * (2 * K));

    float2 vA[NP], vB[NP];
    load_f2<K, DELTA>(xin, vA);                 // cin 0

#pragma unroll 1
    for (int c = 0; c < 32; c += 2) {
        load_f2<K, DELTA>(xin + (c + 1) * WPAD, vB);   // prefetch cin c+1
        {
            const ull* w0 = wbase + c * K;
            ull wp[K];
#pragma unroll
            for (int t = 0; t < K; ++t) wp[t] = w0[t];
            fma_f2<K, DELTA>(vA, wp, acc);             // compute cin c
        }
        if (c + 2 < 32)
            load_f2<K, DELTA>(xin + (c + 2) * WPAD, vA);  // prefetch cin c+2
        {
            const ull* w1 = wbase + (c + 1) * K;
            ull wp[K];
#pragma unroll
            for (int t = 0; t < K; ++t) wp[t] = w1[t];
            fma_f2<K, DELTA>(vB, wp, acc);             // compute cin c+1
        }
    }
    store_outputs<WOUT, LOFF>(sout, acc, sc, sh, bi, cp, j, seq_base);
}

__global__ void __launch_bounds__(NTHREADS, 1)
dna_fused_kernel(Ptrs P, float* __restrict__ out)
{
    extern __shared__ float sm[];
    const int tid = threadIdx.x;
    const int ts  = blockIdx.x * TSIZE;
    const int b   = blockIdx.y;
    const int seq_base = ts - HALO;

    float* bufA = sm + OFF_BUFA;
    float* bufB = sm + OFF_BUFB;
    float* sW[4] = { sm + OFF_W0, sm + OFF_W1, sm + OFF_W2, sm + OFF_W3 };
    float* sSC = sm + OFF_SC;
    float* sSH = sm + OFF_SH;
    float* sBI = sm + OFF_BI;
    float* sFW1 = sm + OFF_FW1;
    float* sFB1 = sm + OFF_FB1;
    float* sFW2 = sm + OFF_FW2;
    float* sFB2 = sm + OFF_FB2;

    // phase 1: halo-only zero fill of both activation buffers.
    {
        constexpr int ZPR = 8 + (WPAD - 512);   // 88 zeros per row
        for (int idx = tid; idx < 64 * ZPR; idx += NTHREADS) {
            int r = idx / ZPR, c = idx - r * ZPR;
            int u = (c < 8) ? c : (504 + c);
            sm[r * WPAD + u] = 0.f;
        }
    }

    const int cinK[4] = { 4 * 3, 32 * 3, 32 * 5, 32 * 7 };
#pragma unroll
    for (int l = 0; l < 4; ++l) {
        const int n = cinK[l];
        for (int i = tid; i < 16 * n; i += NTHREADS) {
            int cp = i / n, r = i - cp * n;
            sW[l][2 * i]     = P.w[l][(2 * cp)     * n + r];
            sW[l][2 * i + 1] = P.w[l][(2 * cp + 1) * n + r];
        }
    }

    for (int i = tid; i < 16 * 32; i += NTHREADS) sFW1[i] = P.fw1[i];
    if (tid < 16) { sFB1[tid] = P.fb1[tid]; sFW2[tid] = P.fw2[tid]; }
    if (tid == 0) sFB2[0] = P.fb2[0];

    if (tid < 128) {
        int l = tid >> 5, c = tid & 31;
        float inv = P.g[l][c] * rsqrtf(P.rv[l][c] + 1e-5f);
        sSC[tid] = inv;
        sSH[tid] = P.bb[l][c] - P.rm[l][c] * inv;
        sBI[tid] = P.b[l][c];
    }
    __syncthreads();

    // phase 2: input tile (4 channels, width 526) over the zeroed halo
    constexpr int WIN = TSIZE + 2 * HALO;   // 526
    for (int idx = tid; idx < 4 * WIN; idx += NTHREADS) {
        int cin = idx / WIN;
        int u = idx - cin * WIN;
        int seq = seq_base + u;
        if (seq >= 0 && seq < SEQ)
            bufA[cin * WPAD + u] = P.x[(b * 4 + cin) * SEQ + seq];
    }
    __syncthreads();

    const int cp = tid >> 5;    // warp -> channel pair [0,16)
    const int j  = tid & 31;    // lane -> 18-pos slice [0,32)

    conv_layer_l1<3, 524, 1>(bufA, bufB, sW[0], sSC +  0, sSH +  0, sBI +  0, cp, j, seq_base);
    __syncthreads();
    conv_layer_pf<3, 522, 2>(bufB, bufA, sW[1], sSC + 32, sSH + 32, sBI + 32, cp, j, seq_base);
    __syncthreads();
    conv_layer_pf<5, 518, 4>(bufA, bufB, sW[2], sSC + 64, sSH + 64, sBI + 64, cp, j, seq_base);
    __syncthreads();
    conv_layer_pf<7, 512, 7>(bufB, bufA, sW[3], sSC + 96, sSH + 96, sBI + 96, cp, j, seq_base);
    __syncthreads();

    // ---- per-position MLP: 32 -> 16 (ReLU) -> 1 ; one thread per position ----
    float yc[32];
#pragma unroll
    for (int c = 0; c < 32; ++c) yc[c] = bufA[c * WPAD + HALO + tid];

    float o = sFB2[0];
#pragma unroll
    for (int i = 0; i < 16; ++i) {
        float h = sFB1[i];
#pragma unroll
        for (int c = 0; c < 32; ++c) h = fmaf(sFW1[i * 32 + c], yc[c], h);
        o = fmaf(fmaxf(h, 0.f), sFW2[i], o);
    }
    out[b * SEQ + ts + tid] = o;
}

extern "C" void kernel_launch(void* const* d_in, const int* in_sizes, int n_in,
                              void* d_out, int out_size)
{
    Ptrs P;
    P.x = (const float*)d_in[0];
    for (int l = 0; l < 4; ++l) {
        P.w[l]  = (const float*)d_in[1 + 6 * l];
        P.b[l]  = (const float*)d_in[2 + 6 * l];
        P.g[l]  = (const float*)d_in[3 + 6 * l];
        P.bb[l] = (const float*)d_in[4 + 6 * l];
        P.rm[l] = (const float*)d_in[5 + 6 * l];
        P.rv[l] = (const float*)d_in[6 + 6 * l];
    }
    P.fw1 = (const float*)d_in[25];
    P.fb1 = (const float*)d_in[26];
    P.fw2 = (const float*)d_in[27];
    P.fb2 = (const float*)d_in[28];

    cudaFuncSetAttribute(dna_fused_kernel,
                         cudaFuncAttributeMaxDynamicSharedMemorySize, SMEM_BYTES);

    dim3 grid(SEQ / TSIZE, BATCH);
    dna_fused_kernel<<<grid, NTHREADS, SMEM_BYTES>>>(P, (float*)d_out);
}